// round 1
// baseline (speedup 1.0000x reference)
#include <cuda_runtime.h>
#include <cstddef>

#define DEVF __device__ __forceinline__

static const int D = 512;

// ---------------- scratch (device globals; no allocations allowed) ----------
__device__ float g_q  [3200 * 512];
__device__ float g_k  [12288 * 512];
__device__ float g_v  [12288 * 512];
__device__ float g_ctx[3200 * 512];
__device__ float g_x1 [3200 * 512];
__device__ float g_x2 [3200 * 512];
__device__ float g_tmp[3200 * 512];
__device__ float g_ybuf0[128 * 512 * 25];
__device__ float g_ybuf1[128 * 512 * 25];
__device__ float g_yt [3200 * 512];

// ---------------- activations ------------------------------------------------
DEVF float fsig(float x) { return 1.f / (1.f + __expf(-x)); }
DEVF float ftanh(float x) {
    float ax = fabsf(x);
    float e  = __expf(-2.f * ax);
    float t  = __fdividef(1.f - e, 1.f + e);
    return copysignf(t, x);
}

// ---------------- generic GEMM: C[M,512] = A[M,512] @ W (+bias)(+res) --------
// TRANSW=false: W stored [K,N] (x @ W). TRANSW=true: W stored [N,K] (A @ W^T).
template<bool TRANSW>
__global__ void __launch_bounds__(256) gemm_kernel(
    const float* __restrict__ A, const float* __restrict__ W,
    const float* __restrict__ bias, const float* __restrict__ res,
    float* __restrict__ C, int M)
{
    const int K = 512;
    __shared__ __align__(16) float As[16][64];
    __shared__ __align__(16) float Bs[16][64];
    int tid = threadIdx.x;
    int bm = blockIdx.x * 64;
    int bn = blockIdx.y * 64;
    int tx = tid & 15, ty = tid >> 4;

    float acc[4][4] = {};

    int a_m = tid >> 2;           // 0..63
    int a_k = (tid & 3) * 4;      // 0,4,8,12

    for (int k0 = 0; k0 < K; k0 += 16) {
        float4 av = *(const float4*)(A + (size_t)(bm + a_m) * K + k0 + a_k);
        As[a_k + 0][a_m] = av.x; As[a_k + 1][a_m] = av.y;
        As[a_k + 2][a_m] = av.z; As[a_k + 3][a_m] = av.w;
        if (!TRANSW) {
            int b_k = tid >> 4;          // 0..15
            int b_n = (tid & 15) * 4;
            float4 bv = *(const float4*)(W + (size_t)(k0 + b_k) * D + bn + b_n);
            *(float4*)&Bs[b_k][b_n] = bv;
        } else {
            int b_n = tid >> 2;          // 0..63
            int b_k = (tid & 3) * 4;
            float4 bv = *(const float4*)(W + (size_t)(bn + b_n) * K + k0 + b_k);
            Bs[b_k + 0][b_n] = bv.x; Bs[b_k + 1][b_n] = bv.y;
            Bs[b_k + 2][b_n] = bv.z; Bs[b_k + 3][b_n] = bv.w;
        }
        __syncthreads();
        #pragma unroll
        for (int k = 0; k < 16; k++) {
            float4 a4 = *(const float4*)&As[k][ty * 4];
            float4 b4 = *(const float4*)&Bs[k][tx * 4];
            float a[4] = {a4.x, a4.y, a4.z, a4.w};
            float b[4] = {b4.x, b4.y, b4.z, b4.w};
            #pragma unroll
            for (int i = 0; i < 4; i++)
                #pragma unroll
                for (int j = 0; j < 4; j++)
                    acc[i][j] += a[i] * b[j];
        }
        __syncthreads();
    }

    #pragma unroll
    for (int i = 0; i < 4; i++) {
        int m = bm + ty * 4 + i;
        #pragma unroll
        for (int j = 0; j < 4; j++) {
            int n = bn + tx * 4 + j;
            float v = acc[i][j] + bias[n];
            if (res) v += res[(size_t)m * D + n];
            C[(size_t)m * D + n] = v;
        }
    }
}

// ---------------- attention core: one block per (b, h) ----------------------
// L=25, E=64, S = 25 (self) or 96 (cross)
__global__ void __launch_bounds__(128) attn_kernel(
    const float* __restrict__ Q, const float* __restrict__ Kp,
    const float* __restrict__ Vp, float* __restrict__ O, int S)
{
    __shared__ float qs[25 * 64];
    __shared__ float kv[96 * 64];
    __shared__ float sc[25 * 96];
    int b = blockIdx.x >> 3, h = blockIdx.x & 7;
    int tid = threadIdx.x;
    const float scale = 0.125f;  // 1/sqrt(64)
    size_t qbase = (size_t)b * 25 * 512 + h * 64;
    size_t kbase = (size_t)b * S  * 512 + h * 64;

    for (int i = tid; i < 25 * 64; i += 128) qs[i] = Q[qbase + (size_t)(i >> 6) * 512 + (i & 63)];
    for (int i = tid; i < S  * 64; i += 128) kv[i] = Kp[kbase + (size_t)(i >> 6) * 512 + (i & 63)];
    __syncthreads();

    for (int i = tid; i < 25 * S; i += 128) {
        int l = i / S, s = i - l * S;
        float acc = 0.f;
        #pragma unroll 16
        for (int e = 0; e < 64; e++) acc += qs[l * 64 + e] * kv[s * 64 + e];
        sc[i] = acc * scale;
    }
    __syncthreads();

    int warp = tid >> 5, lane = tid & 31;
    for (int l = warp; l < 25; l += 4) {
        float mx = -1e30f;
        for (int s = lane; s < S; s += 32) mx = fmaxf(mx, sc[l * S + s]);
        #pragma unroll
        for (int o = 16; o; o >>= 1) mx = fmaxf(mx, __shfl_xor_sync(~0u, mx, o));
        float sum = 0.f;
        for (int s = lane; s < S; s += 32) {
            float e = __expf(sc[l * S + s] - mx);
            sc[l * S + s] = e; sum += e;
        }
        #pragma unroll
        for (int o = 16; o; o >>= 1) sum += __shfl_xor_sync(~0u, sum, o);
        float inv = __fdividef(1.f, sum);
        for (int s = lane; s < S; s += 32) sc[l * S + s] *= inv;
    }
    __syncthreads();

    for (int i = tid; i < S * 64; i += 128) kv[i] = Vp[kbase + (size_t)(i >> 6) * 512 + (i & 63)];
    __syncthreads();

    for (int i = tid; i < 25 * 64; i += 128) {
        int l = i >> 6, e = i & 63;
        float acc = 0.f;
        for (int s = 0; s < S; s++) acc += sc[l * S + s] * kv[s * 64 + e];
        O[qbase + (size_t)l * 512 + e] = acc;
    }
}

// ---------------- LayerNorm over rows of 512 (warp per row) ------------------
__global__ void __launch_bounds__(256) ln_kernel(
    const float* __restrict__ in, const float* __restrict__ g,
    const float* __restrict__ bb, float* __restrict__ out, int M)
{
    int row = blockIdx.x * 8 + (threadIdx.x >> 5);
    int lane = threadIdx.x & 31;
    if (row >= M) return;
    const float* p = in + (size_t)row * 512;
    float v[16];
    float s = 0.f, s2 = 0.f;
    #pragma unroll
    for (int i = 0; i < 16; i++) {
        v[i] = p[lane + 32 * i];
        s += v[i]; s2 += v[i] * v[i];
    }
    #pragma unroll
    for (int o = 16; o; o >>= 1) {
        s  += __shfl_xor_sync(~0u, s,  o);
        s2 += __shfl_xor_sync(~0u, s2, o);
    }
    float mean = s * (1.f / 512.f);
    float var  = s2 * (1.f / 512.f) - mean * mean;
    float rstd = rsqrtf(var + 1e-5f);
    float* q = out + (size_t)row * 512;
    #pragma unroll
    for (int i = 0; i < 16; i++) {
        int d = lane + 32 * i;
        q[d] = (v[i] - mean) * rstd * g[d] + bb[d];
    }
}

// ---------------- transposes -------------------------------------------------
// x2 [b,l,d] -> y0 [b,d,l]
__global__ void transpose_to_tl(const float* __restrict__ in, float* __restrict__ out) {
    int idx = blockIdx.x * 256 + threadIdx.x;
    if (idx >= 128 * 512 * 25) return;
    int l = idx % 25;
    int d = (idx / 25) % 512;
    int b = idx / (25 * 512);
    out[idx] = in[(size_t)b * 12800 + (size_t)l * 512 + d];
}
// y [b,c,l] -> yt [(b,l),c]
__global__ void transpose_to_ld(const float* __restrict__ in, float* __restrict__ out) {
    int idx = blockIdx.x * 256 + threadIdx.x;
    if (idx >= 128 * 25 * 512) return;
    int c = idx % 512;
    int l = (idx / 512) % 25;
    int b = idx / 12800;
    out[idx] = in[(size_t)b * 12800 + (size_t)c * 25 + l];
}

// ---------------- LSTM: one block per batch element, 32 layers ---------------
// gates order: i [0:25), f [25:50), g [50:75), o [75:100)
__global__ void __launch_bounds__(128) lstm_kernel(
    const float* __restrict__ Wih, const float* __restrict__ Whh,
    const float* __restrict__ bih, const float* __restrict__ bhh,
    float* __restrict__ bufA, float* __restrict__ bufB)
{
    int b = blockIdx.x;
    int j = threadIdx.x;
    __shared__ float xs[2][32];
    __shared__ float hs[32];
    __shared__ float gs[100];

    float wih[25], whh[25];

    for (int l = 0; l < 32; l++) {
        const float* in   = ((l & 1) ? bufB : bufA) + (size_t)b * 12800;
        float*       outp = ((l & 1) ? bufA : bufB) + (size_t)b * 12800;

        float bsum = 0.f;
        if (j < 100) {
            const float* wi = Wih + (size_t)l * 2500 + j * 25;
            const float* wh = Whh + (size_t)l * 2500 + j * 25;
            #pragma unroll
            for (int k = 0; k < 25; k++) { wih[k] = wi[k]; whh[k] = wh[k]; }
            bsum = bih[l * 100 + j] + bhh[l * 100 + j];
        }
        if (j < 25) { hs[j] = 0.f; xs[0][j] = in[j]; }
        float creg = 0.f;
        __syncthreads();

        for (int t = 0; t < 512; t++) {
            int par = t & 1;
            if (j < 100) {
                float a0 = bsum, a1 = 0.f;
                #pragma unroll
                for (int k = 0; k < 25; k++) {
                    float p = xs[par][k] * wih[k];
                    if (k & 1) a1 += p; else a0 += p;
                }
                #pragma unroll
                for (int k = 0; k < 25; k++) {
                    float p = hs[k] * whh[k];
                    if (k & 1) a1 += p; else a0 += p;
                }
                float z = a0 + a1;
                float act = (j >= 50 && j < 75) ? ftanh(z) : fsig(z);
                gs[j] = act;
            } else if (j < 125) {
                if (t + 1 < 512) xs[par ^ 1][j - 100] = in[(size_t)(t + 1) * 25 + (j - 100)];
            }
            __syncthreads();
            if (j < 25) {
                float c = gs[25 + j] * creg + gs[j] * gs[50 + j];
                creg = c;
                float h = gs[75 + j] * ftanh(c);
                hs[j] = h;
                outp[(size_t)t * 25 + j] = h;
            }
            __syncthreads();
        }
        __syncthreads();
    }
}

// ---------------- launcher ---------------------------------------------------
extern "C" void kernel_launch(void* const* d_in, const int* in_sizes, int n_in,
                              void* d_out, int out_size)
{
    const float* x     = (const float*)d_in[0];
    const float* cross = (const float*)d_in[1];
    const float* Wq_s = (const float*)d_in[2];  const float* bq_s = (const float*)d_in[3];
    const float* Wk_s = (const float*)d_in[4];  const float* bk_s = (const float*)d_in[5];
    const float* Wv_s = (const float*)d_in[6];  const float* bv_s = (const float*)d_in[7];
    const float* Wo_s = (const float*)d_in[8];  const float* bo_s = (const float*)d_in[9];
    const float* Wq_c = (const float*)d_in[10]; const float* bq_c = (const float*)d_in[11];
    const float* Wk_c = (const float*)d_in[12]; const float* bk_c = (const float*)d_in[13];
    const float* Wv_c = (const float*)d_in[14]; const float* bv_c = (const float*)d_in[15];
    const float* Wo_c = (const float*)d_in[16]; const float* bo_c = (const float*)d_in[17];
    const float* g1 = (const float*)d_in[18]; const float* b1 = (const float*)d_in[19];
    const float* g2 = (const float*)d_in[20]; const float* b2 = (const float*)d_in[21];
    const float* g3 = (const float*)d_in[22]; const float* b3 = (const float*)d_in[23];
    const float* W_ih = (const float*)d_in[24];
    const float* W_hh = (const float*)d_in[25];
    const float* b_ih = (const float*)d_in[26];
    const float* b_hh = (const float*)d_in[27];
    const float* Wc = (const float*)d_in[28]; const float* bc = (const float*)d_in[29];
    float* out = (float*)d_out;

    float *gq, *gk, *gv, *gctx, *gx1, *gx2, *gtmp, *gy0, *gy1, *gyt;
    cudaGetSymbolAddress((void**)&gq,   g_q);
    cudaGetSymbolAddress((void**)&gk,   g_k);
    cudaGetSymbolAddress((void**)&gv,   g_v);
    cudaGetSymbolAddress((void**)&gctx, g_ctx);
    cudaGetSymbolAddress((void**)&gx1,  g_x1);
    cudaGetSymbolAddress((void**)&gx2,  g_x2);
    cudaGetSymbolAddress((void**)&gtmp, g_tmp);
    cudaGetSymbolAddress((void**)&gy0,  g_ybuf0);
    cudaGetSymbolAddress((void**)&gy1,  g_ybuf1);
    cudaGetSymbolAddress((void**)&gyt,  g_yt);

    const int M1 = 3200;    // B*L
    const int M2 = 12288;   // B*S
    dim3 gemmGrid1(M1 / 64, 8);
    dim3 gemmGrid2(M2 / 64, 8);

    // ---- self attention ----
    gemm_kernel<false><<<gemmGrid1, 256>>>(x, Wq_s, bq_s, nullptr, gq, M1);
    gemm_kernel<false><<<gemmGrid1, 256>>>(x, Wk_s, bk_s, nullptr, gk, M1);
    gemm_kernel<false><<<gemmGrid1, 256>>>(x, Wv_s, bv_s, nullptr, gv, M1);
    attn_kernel<<<128 * 8, 128>>>(gq, gk, gv, gctx, 25);
    gemm_kernel<false><<<gemmGrid1, 256>>>(gctx, Wo_s, bo_s, x, gtmp, M1);
    ln_kernel<<<M1 / 8, 256>>>(gtmp, g1, b1, gx1, M1);

    // ---- cross attention ----
    gemm_kernel<false><<<gemmGrid1, 256>>>(gx1, Wq_c, bq_c, nullptr, gq, M1);
    gemm_kernel<false><<<gemmGrid2, 256>>>(cross, Wk_c, bk_c, nullptr, gk, M2);
    gemm_kernel<false><<<gemmGrid2, 256>>>(cross, Wv_c, bv_c, nullptr, gv, M2);
    attn_kernel<<<128 * 8, 128>>>(gq, gk, gv, gctx, 96);
    gemm_kernel<false><<<gemmGrid1, 256>>>(gctx, Wo_c, bo_c, gx1, gtmp, M1);
    ln_kernel<<<M1 / 8, 256>>>(gtmp, g2, b2, gx2, M1);

    // ---- LSTM stack over feature axis ----
    transpose_to_tl<<<(128 * 512 * 25 + 255) / 256, 256>>>(gx2, gy0);
    lstm_kernel<<<128, 128>>>(W_ih, W_hh, b_ih, b_hh, gy0, gy1);
    // 32 layers: final output lands in gy0

    // ---- pointwise conv + residual + final LN ----
    transpose_to_ld<<<(128 * 25 * 512 + 255) / 256, 256>>>(gy0, gyt);
    gemm_kernel<true><<<gemmGrid1, 256>>>(gyt, Wc, bc, gx2, gtmp, M1);
    ln_kernel<<<M1 / 8, 256>>>(gtmp, g3, b3, out, M1);
}

// round 3
// speedup vs baseline: 1.4726x; 1.4726x over previous
#include <cuda_runtime.h>
#include <cstddef>

#define DEVF __device__ __forceinline__

static const int D = 512;

// ---------------- scratch (device globals; no allocations allowed) ----------
__device__ float g_q  [3200 * 512];
__device__ float g_k  [12288 * 512];
__device__ float g_v  [12288 * 512];
__device__ float g_ctx[3200 * 512];
__device__ float g_x1 [3200 * 512];
__device__ float g_x2 [3200 * 512];
__device__ float g_tmp[3200 * 512];
__device__ float g_yt [3200 * 512];

// LSTM wavefront buffers: Y[l][t][b][25], l = 0..32
#define YSTRIDE 1638400   // 512*128*25
__device__ float g_Y[33ull * YSTRIDE];
__device__ int   g_flags[33 * 4 * 32];   // (layer,chunk) progress, padded 128B

// ---------------- f32x2 packed helpers ---------------------------------------
DEVF void fma2(unsigned long long& d, unsigned long long a, unsigned long long b) {
    asm("fma.rn.f32x2 %0, %1, %2, %0;" : "+l"(d) : "l"(a), "l"(b));
}
DEVF unsigned long long splat2(float x) {
    unsigned long long r; unsigned ix = __float_as_uint(x);
    asm("mov.b64 %0, {%1, %1};" : "=l"(r) : "r"(ix));
    return r;
}
DEVF float2 unpack2(unsigned long long v) {
    unsigned lo, hi;
    asm("mov.b64 {%0, %1}, %2;" : "=r"(lo), "=r"(hi) : "l"(v));
    return make_float2(__uint_as_float(lo), __uint_as_float(hi));
}

// ---------------- activations ------------------------------------------------
DEVF float fsig(float x) { return 1.f / (1.f + __expf(-x)); }
DEVF float ftanh(float x) {
    float ax = fabsf(x);
    float e  = __expf(-2.f * ax);
    float t  = __fdividef(1.f - e, 1.f + e);
    return copysignf(t, x);
}

// ---------------- GEMM: C[M,512] = A[M,512] @ W (+bias)(+res), f32x2 ---------
// TRANSW=false: W stored [K,N] (x @ W). TRANSW=true: W stored [N,K] (A @ W^T).
// Tile 128x64, 256 threads, 8x4 micro (4 m-pairs x 4 n).
template<bool TRANSW>
__global__ void __launch_bounds__(256) gemm2_kernel(
    const float* __restrict__ A, const float* __restrict__ W,
    const float* __restrict__ bias, const float* __restrict__ res,
    float* __restrict__ C, int M)
{
    __shared__ __align__(16) float As[16][128];
    __shared__ __align__(16) float Bs[16][64];
    int tid = threadIdx.x;
    int bm = blockIdx.x * 128, bn = blockIdx.y * 64;
    int tx = tid & 15, ty = tid >> 4;

    unsigned long long acc[4][4];
    #pragma unroll
    for (int i = 0; i < 4; i++)
        #pragma unroll
        for (int j = 0; j < 4; j++) acc[i][j] = 0ull;

    int ar = tid >> 1;           // 0..127
    int ac = (tid & 1) * 8;      // 0 or 8
    const float* Arow = A + (size_t)(bm + ar) * 512 + ac;

    for (int k0 = 0; k0 < 512; k0 += 16) {
        float4 a0 = *(const float4*)(Arow + k0);
        float4 a1 = *(const float4*)(Arow + k0 + 4);
        As[ac + 0][ar] = a0.x; As[ac + 1][ar] = a0.y;
        As[ac + 2][ar] = a0.z; As[ac + 3][ar] = a0.w;
        As[ac + 4][ar] = a1.x; As[ac + 5][ar] = a1.y;
        As[ac + 6][ar] = a1.z; As[ac + 7][ar] = a1.w;
        if (!TRANSW) {
            int kk = tid >> 4, nn = (tid & 15) * 4;
            *(float4*)&Bs[kk][nn] = *(const float4*)(W + (size_t)(k0 + kk) * 512 + bn + nn);
        } else {
            int nn = tid >> 2, kq = (tid & 3) * 4;
            float4 bv = *(const float4*)(W + (size_t)(bn + nn) * 512 + k0 + kq);
            Bs[kq + 0][nn] = bv.x; Bs[kq + 1][nn] = bv.y;
            Bs[kq + 2][nn] = bv.z; Bs[kq + 3][nn] = bv.w;
        }
        __syncthreads();
        #pragma unroll
        for (int k = 0; k < 16; k++) {
            ulonglong2 a01 = *(const ulonglong2*)&As[k][ty * 8];
            ulonglong2 a23 = *(const ulonglong2*)&As[k][ty * 8 + 4];
            float4 b4 = *(const float4*)&Bs[k][tx * 4];
            unsigned long long bs0 = splat2(b4.x), bs1 = splat2(b4.y);
            unsigned long long bs2 = splat2(b4.z), bs3 = splat2(b4.w);
            fma2(acc[0][0], a01.x, bs0); fma2(acc[0][1], a01.x, bs1);
            fma2(acc[0][2], a01.x, bs2); fma2(acc[0][3], a01.x, bs3);
            fma2(acc[1][0], a01.y, bs0); fma2(acc[1][1], a01.y, bs1);
            fma2(acc[1][2], a01.y, bs2); fma2(acc[1][3], a01.y, bs3);
            fma2(acc[2][0], a23.x, bs0); fma2(acc[2][1], a23.x, bs1);
            fma2(acc[2][2], a23.x, bs2); fma2(acc[2][3], a23.x, bs3);
            fma2(acc[3][0], a23.y, bs0); fma2(acc[3][1], a23.y, bs1);
            fma2(acc[3][2], a23.y, bs2); fma2(acc[3][3], a23.y, bs3);
        }
        __syncthreads();
    }

    float4 bv4 = *(const float4*)(bias + bn + tx * 4);
    float bb[4] = {bv4.x, bv4.y, bv4.z, bv4.w};
    #pragma unroll
    for (int mp = 0; mp < 4; mp++) {
        int m = bm + ty * 8 + mp * 2;
        float r0[4], r1[4];
        #pragma unroll
        for (int n = 0; n < 4; n++) {
            float2 f = unpack2(acc[mp][n]);
            r0[n] = f.x + bb[n];
            r1[n] = f.y + bb[n];
        }
        if (res) {
            float4 q0 = *(const float4*)(res + (size_t)m * 512 + bn + tx * 4);
            float4 q1 = *(const float4*)(res + (size_t)(m + 1) * 512 + bn + tx * 4);
            r0[0] += q0.x; r0[1] += q0.y; r0[2] += q0.z; r0[3] += q0.w;
            r1[0] += q1.x; r1[1] += q1.y; r1[2] += q1.z; r1[3] += q1.w;
        }
        *(float4*)(C + (size_t)m * 512 + bn + tx * 4) = make_float4(r0[0], r0[1], r0[2], r0[3]);
        *(float4*)(C + (size_t)(m + 1) * 512 + bn + tx * 4) = make_float4(r1[0], r1[1], r1[2], r1[3]);
    }
}

// ---------------- attention core: one block per (b, h) ----------------------
__global__ void __launch_bounds__(128) attn_kernel(
    const float* __restrict__ Q, const float* __restrict__ Kp,
    const float* __restrict__ Vp, float* __restrict__ O, int S)
{
    __shared__ float qs[25 * 64];
    __shared__ float kv[96 * 64];
    __shared__ float sc[25 * 96];
    int b = blockIdx.x >> 3, h = blockIdx.x & 7;
    int tid = threadIdx.x;
    const float scale = 0.125f;
    size_t qbase = (size_t)b * 25 * 512 + h * 64;
    size_t kbase = (size_t)b * S  * 512 + h * 64;

    for (int i = tid; i < 25 * 64; i += 128) qs[i] = Q[qbase + (size_t)(i >> 6) * 512 + (i & 63)];
    for (int i = tid; i < S  * 64; i += 128) kv[i] = Kp[kbase + (size_t)(i >> 6) * 512 + (i & 63)];
    __syncthreads();

    for (int i = tid; i < 25 * S; i += 128) {
        int l = i / S, s = i - l * S;
        float acc = 0.f;
        #pragma unroll 16
        for (int e = 0; e < 64; e++) acc += qs[l * 64 + e] * kv[s * 64 + e];
        sc[i] = acc * scale;
    }
    __syncthreads();

    int warp = tid >> 5, lane = tid & 31;
    for (int l = warp; l < 25; l += 4) {
        float mx = -1e30f;
        for (int s = lane; s < S; s += 32) mx = fmaxf(mx, sc[l * S + s]);
        #pragma unroll
        for (int o = 16; o; o >>= 1) mx = fmaxf(mx, __shfl_xor_sync(~0u, mx, o));
        float sum = 0.f;
        for (int s = lane; s < S; s += 32) {
            float e = __expf(sc[l * S + s] - mx);
            sc[l * S + s] = e; sum += e;
        }
        #pragma unroll
        for (int o = 16; o; o >>= 1) sum += __shfl_xor_sync(~0u, sum, o);
        float inv = __fdividef(1.f, sum);
        for (int s = lane; s < S; s += 32) sc[l * S + s] *= inv;
    }
    __syncthreads();

    for (int i = tid; i < S * 64; i += 128) kv[i] = Vp[kbase + (size_t)(i >> 6) * 512 + (i & 63)];
    __syncthreads();

    for (int i = tid; i < 25 * 64; i += 128) {
        int l = i >> 6, e = i & 63;
        float acc = 0.f;
        for (int s = 0; s < S; s++) acc += sc[l * S + s] * kv[s * 64 + e];
        O[qbase + (size_t)l * 512 + e] = acc;
    }
}

// ---------------- LayerNorm over rows of 512 (warp per row) ------------------
__global__ void __launch_bounds__(256) ln_kernel(
    const float* __restrict__ in, const float* __restrict__ g,
    const float* __restrict__ bb, float* __restrict__ out, int M)
{
    int row = blockIdx.x * 8 + (threadIdx.x >> 5);
    int lane = threadIdx.x & 31;
    if (row >= M) return;
    const float* p = in + (size_t)row * 512;
    float v[16];
    float s = 0.f, s2 = 0.f;
    #pragma unroll
    for (int i = 0; i < 16; i++) {
        v[i] = p[lane + 32 * i];
        s += v[i]; s2 += v[i] * v[i];
    }
    #pragma unroll
    for (int o = 16; o; o >>= 1) {
        s  += __shfl_xor_sync(~0u, s,  o);
        s2 += __shfl_xor_sync(~0u, s2, o);
    }
    float mean = s * (1.f / 512.f);
    float var  = s2 * (1.f / 512.f) - mean * mean;
    float rstd = rsqrtf(var + 1e-5f);
    float* q = out + (size_t)row * 512;
    #pragma unroll
    for (int i = 0; i < 16; i++) {
        int d = lane + 32 * i;
        q[d] = (v[i] - mean) * rstd * g[d] + bb[d];
    }
}

// ---------------- transposes -------------------------------------------------
// x2 [b][l][d] -> Y0 [t=d][b][k=l]
__global__ void transpose_in_kernel(const float* __restrict__ in, float* __restrict__ out) {
    int idx = blockIdx.x * 256 + threadIdx.x;
    if (idx >= 128 * 512 * 25) return;
    int l = idx % 25;
    int b = (idx / 25) % 128;
    int d = idx / 3200;
    out[idx] = in[(size_t)b * 12800 + (size_t)l * 512 + d];
}
// Y32 [t=c][b][u=l] -> yt [(b,l)][c]
__global__ void transpose_out_kernel(const float* __restrict__ in, float* __restrict__ out) {
    int idx = blockIdx.x * 256 + threadIdx.x;
    if (idx >= 128 * 25 * 512) return;
    int c = idx % 512;
    int l = (idx / 512) % 25;
    int b = idx / 12800;
    out[idx] = in[(size_t)c * 3200 + b * 25 + l];
}

__global__ void zero_flags_kernel() {
    int i = blockIdx.x * 256 + threadIdx.x;
    if (i < 33 * 4 * 32) g_flags[i] = 0;
}

// ---------------- LSTM wavefront: 128 blocks = 32 layers x 4 chunks ---------
// Y layout: [t][b][25]. Stage (layer, chunk) consumes Y[layer], produces Y[layer+1].
// Per-chunk progress flags give a 544-deep wavefront instead of 16384 serial steps.
__global__ void __launch_bounds__(256) lstm_wave_kernel(
    const float* __restrict__ Wih, const float* __restrict__ Whh,
    const float* __restrict__ bih, const float* __restrict__ bhh)
{
    int layer = blockIdx.x & 31;
    int chunk = blockIdx.x >> 5;
    int b0 = chunk * 32;
    const float* in  = g_Y + (size_t)layer * YSTRIDE;
    float* outp      = g_Y + (size_t)(layer + 1) * YSTRIDE;
    int* inflag  = g_flags + (layer * 4 + chunk) * 32;
    int* outflag = g_flags + ((layer + 1) * 4 + chunk) * 32;

    __shared__ __align__(16) float xh[50][32];     // rows 0..24: x_t, 25..49: h_{t-1}
    __shared__ __align__(16) float gates[100][32];

    int tid = threadIdx.x;

    // gate role: tid<200: gate row j, batch half (16 batches)
    int j = tid >> 1, half = tid & 1, bbase = half << 4;
    float w[50];
    unsigned long long bs2 = 0ull;
    if (tid < 200) {
        const float* wi = Wih + (size_t)layer * 2500 + j * 25;
        const float* wh = Whh + (size_t)layer * 2500 + j * 25;
        #pragma unroll
        for (int k = 0; k < 25; k++) { w[k] = wi[k]; w[25 + k] = wh[k]; }
        bs2 = splat2(bih[layer * 100 + j] + bhh[layer * 100 + j]);
    }
    // update role: tid<200: unit u, batch quad
    int u = tid >> 3, bb = (tid & 7) << 2;
    float4 cst = make_float4(0.f, 0.f, 0.f, 0.f);

    for (int i = tid; i < 25 * 32; i += 256) xh[25 + (i >> 5)][i & 31] = 0.f;
    __syncthreads();

    for (int t = 0; t < 512; t++) {
        if (layer > 0 && tid == 0) {
            int v;
            do {
                asm volatile("ld.acquire.gpu.global.b32 %0, [%1];" : "=r"(v) : "l"(inflag) : "memory");
            } while (v < t + 1);
        }
        __syncthreads();

        // load x slice (coalesced: k fastest)
        const float* xin = in + (size_t)t * 3200 + b0 * 25;
        for (int i = tid; i < 800; i += 256) {
            int b = i / 25, k = i - b * 25;
            xh[k][b] = xin[i];
        }
        __syncthreads();

        if (tid < 200) {
            unsigned long long acc[8];
            #pragma unroll
            for (int q = 0; q < 8; q++) acc[q] = bs2;
            #pragma unroll
            for (int k = 0; k < 50; k++) {
                unsigned long long wp = splat2(w[k]);
                const ulonglong2* row = (const ulonglong2*)&xh[k][bbase];
                ulonglong2 p0 = row[0], p1 = row[1], p2 = row[2], p3 = row[3];
                fma2(acc[0], p0.x, wp); fma2(acc[1], p0.y, wp);
                fma2(acc[2], p1.x, wp); fma2(acc[3], p1.y, wp);
                fma2(acc[4], p2.x, wp); fma2(acc[5], p2.y, wp);
                fma2(acc[6], p3.x, wp); fma2(acc[7], p3.y, wp);
            }
            float g16[16];
            #pragma unroll
            for (int q = 0; q < 8; q++) {
                float2 f = unpack2(acc[q]);
                g16[2 * q] = f.x; g16[2 * q + 1] = f.y;
            }
            bool isg = (j >= 50 && j < 75);
            #pragma unroll
            for (int i = 0; i < 16; i++) g16[i] = isg ? ftanh(g16[i]) : fsig(g16[i]);
            float4* gp = (float4*)&gates[j][bbase];
            gp[0] = make_float4(g16[0],  g16[1],  g16[2],  g16[3]);
            gp[1] = make_float4(g16[4],  g16[5],  g16[6],  g16[7]);
            gp[2] = make_float4(g16[8],  g16[9],  g16[10], g16[11]);
            gp[3] = make_float4(g16[12], g16[13], g16[14], g16[15]);
        }
        __syncthreads();

        if (tid < 200) {
            float4 gi = *(const float4*)&gates[u     ][bb];
            float4 gf = *(const float4*)&gates[u + 25][bb];
            float4 gg = *(const float4*)&gates[u + 50][bb];
            float4 go = *(const float4*)&gates[u + 75][bb];
            cst.x = gf.x * cst.x + gi.x * gg.x;
            cst.y = gf.y * cst.y + gi.y * gg.y;
            cst.z = gf.z * cst.z + gi.z * gg.z;
            cst.w = gf.w * cst.w + gi.w * gg.w;
            float h0 = go.x * ftanh(cst.x);
            float h1 = go.y * ftanh(cst.y);
            float h2 = go.z * ftanh(cst.z);
            float h3 = go.w * ftanh(cst.w);
            *(float4*)&xh[25 + u][bb] = make_float4(h0, h1, h2, h3);
            float* op = outp + (size_t)t * 3200 + (b0 + bb) * 25 + u;
            op[0] = h0; op[25] = h1; op[50] = h2; op[75] = h3;
            __threadfence();
        }
        __syncthreads();
        if (tid == 0) {
            int nv = t + 1;
            asm volatile("st.release.gpu.global.b32 [%0], %1;" :: "l"(outflag), "r"(nv) : "memory");
        }
    }
}

// ---------------- launcher ---------------------------------------------------
extern "C" void kernel_launch(void* const* d_in, const int* in_sizes, int n_in,
                              void* d_out, int out_size)
{
    const float* x     = (const float*)d_in[0];
    const float* cross = (const float*)d_in[1];
    const float* Wq_s = (const float*)d_in[2];  const float* bq_s = (const float*)d_in[3];
    const float* Wk_s = (const float*)d_in[4];  const float* bk_s = (const float*)d_in[5];
    const float* Wv_s = (const float*)d_in[6];  const float* bv_s = (const float*)d_in[7];
    const float* Wo_s = (const float*)d_in[8];  const float* bo_s = (const float*)d_in[9];
    const float* Wq_c = (const float*)d_in[10]; const float* bq_c = (const float*)d_in[11];
    const float* Wk_c = (const float*)d_in[12]; const float* bk_c = (const float*)d_in[13];
    const float* Wv_c = (const float*)d_in[14]; const float* bv_c = (const float*)d_in[15];
    const float* Wo_c = (const float*)d_in[16]; const float* bo_c = (const float*)d_in[17];
    const float* g1 = (const float*)d_in[18]; const float* b1 = (const float*)d_in[19];
    const float* g2 = (const float*)d_in[20]; const float* b2 = (const float*)d_in[21];
    const float* g3 = (const float*)d_in[22]; const float* b3 = (const float*)d_in[23];
    const float* W_ih = (const float*)d_in[24];
    const float* W_hh = (const float*)d_in[25];
    const float* b_ih = (const float*)d_in[26];
    const float* b_hh = (const float*)d_in[27];
    const float* Wc = (const float*)d_in[28]; const float* bc = (const float*)d_in[29];
    float* out = (float*)d_out;

    float *gq, *gk, *gv, *gctx, *gx1, *gx2, *gtmp, *gyt, *gY;
    cudaGetSymbolAddress((void**)&gq,   g_q);
    cudaGetSymbolAddress((void**)&gk,   g_k);
    cudaGetSymbolAddress((void**)&gv,   g_v);
    cudaGetSymbolAddress((void**)&gctx, g_ctx);
    cudaGetSymbolAddress((void**)&gx1,  g_x1);
    cudaGetSymbolAddress((void**)&gx2,  g_x2);
    cudaGetSymbolAddress((void**)&gtmp, g_tmp);
    cudaGetSymbolAddress((void**)&gyt,  g_yt);
    cudaGetSymbolAddress((void**)&gY,   g_Y);

    const int M1 = 3200;    // B*L
    const int M2 = 12288;   // B*S
    dim3 grid1(M1 / 128, 8);
    dim3 grid2(M2 / 128, 8);

    zero_flags_kernel<<<17, 256>>>();

    // ---- self attention ----
    gemm2_kernel<false><<<grid1, 256>>>(x, Wq_s, bq_s, nullptr, gq, M1);
    gemm2_kernel<false><<<grid1, 256>>>(x, Wk_s, bk_s, nullptr, gk, M1);
    gemm2_kernel<false><<<grid1, 256>>>(x, Wv_s, bv_s, nullptr, gv, M1);
    attn_kernel<<<128 * 8, 128>>>(gq, gk, gv, gctx, 25);
    gemm2_kernel<false><<<grid1, 256>>>(gctx, Wo_s, bo_s, x, gtmp, M1);
    ln_kernel<<<M1 / 8, 256>>>(gtmp, g1, b1, gx1, M1);

    // ---- cross attention ----
    gemm2_kernel<false><<<grid1, 256>>>(gx1, Wq_c, bq_c, nullptr, gq, M1);
    gemm2_kernel<false><<<grid2, 256>>>(cross, Wk_c, bk_c, nullptr, gk, M2);
    gemm2_kernel<false><<<grid2, 256>>>(cross, Wv_c, bv_c, nullptr, gv, M2);
    attn_kernel<<<128 * 8, 128>>>(gq, gk, gv, gctx, 96);
    gemm2_kernel<false><<<grid1, 256>>>(gctx, Wo_c, bo_c, gx1, gtmp, M1);
    ln_kernel<<<M1 / 8, 256>>>(gtmp, g2, b2, gx2, M1);

    // ---- LSTM wavefront over feature axis ----
    transpose_in_kernel<<<(128 * 512 * 25 + 255) / 256, 256>>>(gx2, gY);
    lstm_wave_kernel<<<128, 256>>>(W_ih, W_hh, b_ih, b_hh);

    // ---- pointwise conv + residual + final LN ----
    transpose_out_kernel<<<(128 * 25 * 512 + 255) / 256, 256>>>(gY + 32ull * YSTRIDE, gyt);
    gemm2_kernel<true><<<grid1, 256>>>(gyt, Wc, bc, gx2, gtmp, M1);
    ln_kernel<<<M1 / 8, 256>>>(gtmp, g3, b3, out, M1);
}

// round 4
// speedup vs baseline: 2.2486x; 1.5270x over previous
#include <cuda_runtime.h>
#include <cstddef>

#define DEVF __device__ __forceinline__

// ---------------- scratch (device globals; no allocations allowed) ----------
__device__ float g_q  [3200 * 512];
__device__ float g_k  [12288 * 512];
__device__ float g_v  [12288 * 512];
__device__ float g_ctx[3200 * 512];
__device__ float g_x1 [3200 * 512];
__device__ float g_x2 [3200 * 512];
__device__ float g_tmp[3200 * 512];
__device__ float g_yt [3200 * 512];

// LSTM wavefront buffers: Y[l][t][k][b], l = 0..32, t<512, k<25, b<128
#define YSTRIDE 1638400   // 512*25*128
__device__ float g_Y[33ull * YSTRIDE];
__device__ int   g_flags[33 * 4 * 32];   // (layer,chunk) progress, 128B padded

// ---------------- f32x2 packed helpers ---------------------------------------
DEVF void fma2(unsigned long long& d, unsigned long long a, unsigned long long b) {
    asm("fma.rn.f32x2 %0, %1, %2, %0;" : "+l"(d) : "l"(a), "l"(b));
}
DEVF unsigned long long splat2(float x) {
    unsigned long long r; unsigned ix = __float_as_uint(x);
    asm("mov.b64 %0, {%1, %1};" : "=l"(r) : "r"(ix));
    return r;
}
DEVF float2 unpack2(unsigned long long v) {
    unsigned lo, hi;
    asm("mov.b64 {%0, %1}, %2;" : "=r"(lo), "=r"(hi) : "l"(v));
    return make_float2(__uint_as_float(lo), __uint_as_float(hi));
}

// ---------------- activations ------------------------------------------------
DEVF float fsig(float x) { return 1.f / (1.f + __expf(-x)); }
DEVF float ftanh(float x) {
    float ax = fabsf(x);
    float e  = __expf(-2.f * ax);
    float t  = __fdividef(1.f - e, 1.f + e);
    return copysignf(t, x);
}

// ---------------- double-buffered GEMM core ----------------------------------
// C[.,512] = A[.,512] @ W (+bias)(+res). Tile 128x64, 256 threads, f32x2.
// TRANSW=false: W stored [K,N]. TRANSW=true: W stored [N,K].
template<bool TRANSW>
DEVF void gemm_core(const float* __restrict__ A, const float* __restrict__ W,
                    const float* __restrict__ bias, const float* __restrict__ res,
                    float* __restrict__ C)
{
    __shared__ __align__(16) float As[2][16][128];
    __shared__ __align__(16) float Bs[2][16][64];
    int tid = threadIdx.x;
    int bm = blockIdx.x * 128, bn = blockIdx.y * 64;
    int tx = tid & 15, ty = tid >> 4;

    unsigned long long acc[4][4];
    #pragma unroll
    for (int i = 0; i < 4; i++)
        #pragma unroll
        for (int j = 0; j < 4; j++) acc[i][j] = 0ull;

    int ar = tid >> 1;           // 0..127
    int ac = (tid & 1) * 8;      // 0 or 8
    const float* Arow = A + (size_t)(bm + ar) * 512 + ac;

    int b_kk = tid >> 4, b_nn = (tid & 15) * 4;   // !TRANSW
    int b_n2 = tid >> 2, b_k2 = (tid & 3) * 4;    // TRANSW

    float4 a0, a1, bv;
    // prologue: fetch + store tile 0
    a0 = *(const float4*)(Arow + 0);
    a1 = *(const float4*)(Arow + 4);
    if (!TRANSW) bv = *(const float4*)(W + (size_t)b_kk * 512 + bn + b_nn);
    else         bv = *(const float4*)(W + (size_t)(bn + b_n2) * 512 + b_k2);

    As[0][ac + 0][ar] = a0.x; As[0][ac + 1][ar] = a0.y;
    As[0][ac + 2][ar] = a0.z; As[0][ac + 3][ar] = a0.w;
    As[0][ac + 4][ar] = a1.x; As[0][ac + 5][ar] = a1.y;
    As[0][ac + 6][ar] = a1.z; As[0][ac + 7][ar] = a1.w;
    if (!TRANSW) {
        *(float4*)&Bs[0][b_kk][b_nn] = bv;
    } else {
        Bs[0][b_k2 + 0][b_n2] = bv.x; Bs[0][b_k2 + 1][b_n2] = bv.y;
        Bs[0][b_k2 + 2][b_n2] = bv.z; Bs[0][b_k2 + 3][b_n2] = bv.w;
    }
    __syncthreads();

    #pragma unroll 2
    for (int it = 0; it < 32; it++) {
        int buf = it & 1;
        if (it < 31) {
            int k0 = (it + 1) * 16;
            a0 = *(const float4*)(Arow + k0);
            a1 = *(const float4*)(Arow + k0 + 4);
            if (!TRANSW) bv = *(const float4*)(W + (size_t)(k0 + b_kk) * 512 + bn + b_nn);
            else         bv = *(const float4*)(W + (size_t)(bn + b_n2) * 512 + k0 + b_k2);
        }
        #pragma unroll
        for (int k = 0; k < 16; k++) {
            ulonglong2 a01 = *(const ulonglong2*)&As[buf][k][ty * 8];
            ulonglong2 a23 = *(const ulonglong2*)&As[buf][k][ty * 8 + 4];
            float4 b4 = *(const float4*)&Bs[buf][k][tx * 4];
            unsigned long long bs0 = splat2(b4.x), bs1 = splat2(b4.y);
            unsigned long long bs2 = splat2(b4.z), bs3 = splat2(b4.w);
            fma2(acc[0][0], a01.x, bs0); fma2(acc[0][1], a01.x, bs1);
            fma2(acc[0][2], a01.x, bs2); fma2(acc[0][3], a01.x, bs3);
            fma2(acc[1][0], a01.y, bs0); fma2(acc[1][1], a01.y, bs1);
            fma2(acc[1][2], a01.y, bs2); fma2(acc[1][3], a01.y, bs3);
            fma2(acc[2][0], a23.x, bs0); fma2(acc[2][1], a23.x, bs1);
            fma2(acc[2][2], a23.x, bs2); fma2(acc[2][3], a23.x, bs3);
            fma2(acc[3][0], a23.y, bs0); fma2(acc[3][1], a23.y, bs1);
            fma2(acc[3][2], a23.y, bs2); fma2(acc[3][3], a23.y, bs3);
        }
        if (it < 31) {
            int nb = buf ^ 1;
            As[nb][ac + 0][ar] = a0.x; As[nb][ac + 1][ar] = a0.y;
            As[nb][ac + 2][ar] = a0.z; As[nb][ac + 3][ar] = a0.w;
            As[nb][ac + 4][ar] = a1.x; As[nb][ac + 5][ar] = a1.y;
            As[nb][ac + 6][ar] = a1.z; As[nb][ac + 7][ar] = a1.w;
            if (!TRANSW) {
                *(float4*)&Bs[nb][b_kk][b_nn] = bv;
            } else {
                Bs[nb][b_k2 + 0][b_n2] = bv.x; Bs[nb][b_k2 + 1][b_n2] = bv.y;
                Bs[nb][b_k2 + 2][b_n2] = bv.z; Bs[nb][b_k2 + 3][b_n2] = bv.w;
            }
        }
        __syncthreads();
    }

    float4 bv4 = *(const float4*)(bias + bn + tx * 4);
    float bb[4] = {bv4.x, bv4.y, bv4.z, bv4.w};
    #pragma unroll
    for (int mp = 0; mp < 4; mp++) {
        int m = bm + ty * 8 + mp * 2;
        float r0[4], r1[4];
        #pragma unroll
        for (int n = 0; n < 4; n++) {
            float2 f = unpack2(acc[mp][n]);
            r0[n] = f.x + bb[n];
            r1[n] = f.y + bb[n];
        }
        if (res) {
            float4 q0 = *(const float4*)(res + (size_t)m * 512 + bn + tx * 4);
            float4 q1 = *(const float4*)(res + (size_t)(m + 1) * 512 + bn + tx * 4);
            r0[0] += q0.x; r0[1] += q0.y; r0[2] += q0.z; r0[3] += q0.w;
            r1[0] += q1.x; r1[1] += q1.y; r1[2] += q1.z; r1[3] += q1.w;
        }
        *(float4*)(C + (size_t)m * 512 + bn + tx * 4) = make_float4(r0[0], r0[1], r0[2], r0[3]);
        *(float4*)(C + (size_t)(m + 1) * 512 + bn + tx * 4) = make_float4(r1[0], r1[1], r1[2], r1[3]);
    }
}

struct GemmSet {
    const float* W[3];
    const float* b[3];
    const float* r[3];
    float*       C[3];
};

template<bool TRANSW>
__global__ void __launch_bounds__(256, 2) gemm_db_kernel(const float* __restrict__ A, GemmSet s) {
    int z = blockIdx.z;
    gemm_core<TRANSW>(A, s.W[z], s.b[z], s.r[z], s.C[z]);
}

// ---------------- attention core: one block per (b, h) ----------------------
__global__ void __launch_bounds__(128) attn_kernel(
    const float* __restrict__ Q, const float* __restrict__ Kp,
    const float* __restrict__ Vp, float* __restrict__ O, int S)
{
    __shared__ float qs[25 * 64];
    __shared__ float kv[96 * 64];
    __shared__ float sc[25 * 96];
    int b = blockIdx.x >> 3, h = blockIdx.x & 7;
    int tid = threadIdx.x;
    const float scale = 0.125f;
    size_t qbase = (size_t)b * 25 * 512 + h * 64;
    size_t kbase = (size_t)b * S  * 512 + h * 64;

    for (int i = tid; i < 25 * 64; i += 128) qs[i] = Q[qbase + (size_t)(i >> 6) * 512 + (i & 63)];
    for (int i = tid; i < S  * 64; i += 128) kv[i] = Kp[kbase + (size_t)(i >> 6) * 512 + (i & 63)];
    __syncthreads();

    for (int i = tid; i < 25 * S; i += 128) {
        int l = i / S, s = i - l * S;
        float acc = 0.f;
        #pragma unroll 16
        for (int e = 0; e < 64; e++) acc += qs[l * 64 + e] * kv[s * 64 + e];
        sc[i] = acc * scale;
    }
    __syncthreads();

    int warp = tid >> 5, lane = tid & 31;
    for (int l = warp; l < 25; l += 4) {
        float mx = -1e30f;
        for (int s = lane; s < S; s += 32) mx = fmaxf(mx, sc[l * S + s]);
        #pragma unroll
        for (int o = 16; o; o >>= 1) mx = fmaxf(mx, __shfl_xor_sync(~0u, mx, o));
        float sum = 0.f;
        for (int s = lane; s < S; s += 32) {
            float e = __expf(sc[l * S + s] - mx);
            sc[l * S + s] = e; sum += e;
        }
        #pragma unroll
        for (int o = 16; o; o >>= 1) sum += __shfl_xor_sync(~0u, sum, o);
        float inv = __fdividef(1.f, sum);
        for (int s = lane; s < S; s += 32) sc[l * S + s] *= inv;
    }
    __syncthreads();

    for (int i = tid; i < S * 64; i += 128) kv[i] = Vp[kbase + (size_t)(i >> 6) * 512 + (i & 63)];
    __syncthreads();

    for (int i = tid; i < 25 * 64; i += 128) {
        int l = i >> 6, e = i & 63;
        float acc = 0.f;
        for (int s = 0; s < S; s++) acc += sc[l * S + s] * kv[s * 64 + e];
        O[qbase + (size_t)l * 512 + e] = acc;
    }
}

// ---------------- LayerNorm over rows of 512 (warp per row) ------------------
__global__ void __launch_bounds__(256) ln_kernel(
    const float* __restrict__ in, const float* __restrict__ g,
    const float* __restrict__ bb, float* __restrict__ out, int M)
{
    int row = blockIdx.x * 8 + (threadIdx.x >> 5);
    int lane = threadIdx.x & 31;
    if (row >= M) return;
    const float* p = in + (size_t)row * 512;
    float v[16];
    float s = 0.f, s2 = 0.f;
    #pragma unroll
    for (int i = 0; i < 16; i++) {
        v[i] = p[lane + 32 * i];
        s += v[i]; s2 += v[i] * v[i];
    }
    #pragma unroll
    for (int o = 16; o; o >>= 1) {
        s  += __shfl_xor_sync(~0u, s,  o);
        s2 += __shfl_xor_sync(~0u, s2, o);
    }
    float mean = s * (1.f / 512.f);
    float var  = s2 * (1.f / 512.f) - mean * mean;
    float rstd = rsqrtf(var + 1e-5f);
    float* q = out + (size_t)row * 512;
    #pragma unroll
    for (int i = 0; i < 16; i++) {
        int d = lane + 32 * i;
        q[d] = (v[i] - mean) * rstd * g[d] + bb[d];
    }
}

// ---------------- transposes -------------------------------------------------
// x2 [b][l][d] -> Y0 [t=d][k=l][b]
__global__ void transpose_in_kernel(const float* __restrict__ in, float* __restrict__ out) {
    int idx = blockIdx.x * 256 + threadIdx.x;
    if (idx >= 128 * 512 * 25) return;
    int b = idx & 127;
    int r = idx >> 7;
    int k = r % 25;
    int t = r / 25;
    out[t * 3200 + k * 128 + b] = in[(size_t)b * 12800 + (size_t)k * 512 + t];
}
// Y32 [t=c][u=l][b] -> yt [(b,l)][c]
__global__ void transpose_out_kernel(const float* __restrict__ in, float* __restrict__ out) {
    int idx = blockIdx.x * 256 + threadIdx.x;
    if (idx >= 128 * 25 * 512) return;
    int c = idx & 511;
    int l = (idx >> 9) % 25;
    int b = idx / 12800;
    out[idx] = in[(size_t)c * 3200 + l * 128 + b];
}

__global__ void zero_flags_kernel() {
    int i = blockIdx.x * 256 + threadIdx.x;
    if (i < 33 * 4 * 32) g_flags[i] = 0;
}

DEVF void spinwait(const int* p, int need) {
    int v;
    do {
        asm volatile("ld.acquire.gpu.global.b32 %0, [%1];" : "=r"(v) : "l"(p) : "memory");
    } while (v < need);
}

// ---------------- LSTM wavefront: 128 blocks = 32 layers x 4 chunks ---------
// Y layout: [t][k][b] (b over full 128). Warp 7 = IO warp (flag wait + x prefetch),
// warps 0-6 (tid<200) = gate compute + state update. 2 barriers per step.
__global__ void __launch_bounds__(256) lstm_wave_kernel(
    const float* __restrict__ Wih, const float* __restrict__ Whh,
    const float* __restrict__ bih, const float* __restrict__ bhh)
{
    int layer = blockIdx.x & 31;
    int chunk = blockIdx.x >> 5;
    int b0 = chunk * 32;
    const float* in  = g_Y + (size_t)layer * YSTRIDE;
    float* outp      = g_Y + (size_t)(layer + 1) * YSTRIDE;
    const int* inflag = g_flags + (layer * 4 + chunk) * 32;
    int* outflag      = g_flags + ((layer + 1) * 4 + chunk) * 32;

    __shared__ __align__(16) float xbuf[2][25][32];
    __shared__ __align__(16) float hbuf[25][32];
    __shared__ __align__(16) float gates[100][32];

    int tid = threadIdx.x;
    int warp = tid >> 5, lane = tid & 31;

    // gate role
    int j = tid >> 1, bbase = (tid & 1) << 4;
    float w[50];
    unsigned long long bs2 = 0ull;
    if (tid < 200) {
        const float* wi = Wih + (size_t)layer * 2500 + j * 25;
        const float* wh = Whh + (size_t)layer * 2500 + j * 25;
        #pragma unroll
        for (int k = 0; k < 25; k++) { w[k] = wi[k]; w[25 + k] = wh[k]; }
        bs2 = splat2(bih[layer * 100 + j] + bhh[layer * 100 + j]);
    }
    // update role
    int u = tid >> 3, bb = (tid & 7) << 2;
    float4 cst = make_float4(0.f, 0.f, 0.f, 0.f);

    for (int i = tid; i < 800; i += 256) hbuf[i >> 5][i & 31] = 0.f;

    // prologue: load x_0
    if (warp == 7) {
        if (layer > 0 && lane == 0) spinwait(inflag, 1);
        __syncwarp();
        const float* src = in + b0;
        #pragma unroll
        for (int k = 0; k < 25; k++) xbuf[0][k][lane] = src[k * 128 + lane];
    }
    __syncthreads();

    for (int t = 0; t < 512; t++) {
        int par = t & 1;
        // phase A: gates (warps 0-6) || prefetch x_{t+1} + flag wait (warp 7)
        if (tid < 200) {
            unsigned long long acc[8];
            #pragma unroll
            for (int q = 0; q < 8; q++) acc[q] = bs2;
            #pragma unroll
            for (int k = 0; k < 25; k++) {
                unsigned long long wp = splat2(w[k]);
                const ulonglong2* row = (const ulonglong2*)&xbuf[par][k][bbase];
                ulonglong2 p0 = row[0], p1 = row[1], p2 = row[2], p3 = row[3];
                fma2(acc[0], p0.x, wp); fma2(acc[1], p0.y, wp);
                fma2(acc[2], p1.x, wp); fma2(acc[3], p1.y, wp);
                fma2(acc[4], p2.x, wp); fma2(acc[5], p2.y, wp);
                fma2(acc[6], p3.x, wp); fma2(acc[7], p3.y, wp);
            }
            #pragma unroll
            for (int k = 0; k < 25; k++) {
                unsigned long long wp = splat2(w[25 + k]);
                const ulonglong2* row = (const ulonglong2*)&hbuf[k][bbase];
                ulonglong2 p0 = row[0], p1 = row[1], p2 = row[2], p3 = row[3];
                fma2(acc[0], p0.x, wp); fma2(acc[1], p0.y, wp);
                fma2(acc[2], p1.x, wp); fma2(acc[3], p1.y, wp);
                fma2(acc[4], p2.x, wp); fma2(acc[5], p2.y, wp);
                fma2(acc[6], p3.x, wp); fma2(acc[7], p3.y, wp);
            }
            float g16[16];
            #pragma unroll
            for (int q = 0; q < 8; q++) {
                float2 f = unpack2(acc[q]);
                g16[2 * q] = f.x; g16[2 * q + 1] = f.y;
            }
            bool isg = (j >= 50 && j < 75);
            #pragma unroll
            for (int i = 0; i < 16; i++) g16[i] = isg ? ftanh(g16[i]) : fsig(g16[i]);
            float4* gp = (float4*)&gates[j][bbase];
            gp[0] = make_float4(g16[0],  g16[1],  g16[2],  g16[3]);
            gp[1] = make_float4(g16[4],  g16[5],  g16[6],  g16[7]);
            gp[2] = make_float4(g16[8],  g16[9],  g16[10], g16[11]);
            gp[3] = make_float4(g16[12], g16[13], g16[14], g16[15]);
        } else if (warp == 7) {
            if (t < 511) {
                if (layer > 0 && lane == 0) spinwait(inflag, t + 2);
                __syncwarp();
                const float* src = in + (size_t)(t + 1) * 3200 + b0;
                #pragma unroll
                for (int k = 0; k < 25; k++) xbuf[par ^ 1][k][lane] = src[k * 128 + lane];
            }
        }
        __syncthreads();

        // phase B: state update + publish h
        if (tid < 200) {
            float4 gi = *(const float4*)&gates[u     ][bb];
            float4 gf = *(const float4*)&gates[u + 25][bb];
            float4 gg = *(const float4*)&gates[u + 50][bb];
            float4 go = *(const float4*)&gates[u + 75][bb];
            cst.x = gf.x * cst.x + gi.x * gg.x;
            cst.y = gf.y * cst.y + gi.y * gg.y;
            cst.z = gf.z * cst.z + gi.z * gg.z;
            cst.w = gf.w * cst.w + gi.w * gg.w;
            float4 h4 = make_float4(go.x * ftanh(cst.x), go.y * ftanh(cst.y),
                                    go.z * ftanh(cst.z), go.w * ftanh(cst.w));
            *(float4*)&hbuf[u][bb] = h4;
            *(float4*)(outp + (size_t)t * 3200 + u * 128 + b0 + bb) = h4;
        }
        __syncthreads();
        if (tid == 0) {
            int nv = t + 1;
            asm volatile("st.release.gpu.global.b32 [%0], %1;" :: "l"(outflag), "r"(nv) : "memory");
        }
    }
}

// ---------------- launcher ---------------------------------------------------
extern "C" void kernel_launch(void* const* d_in, const int* in_sizes, int n_in,
                              void* d_out, int out_size)
{
    const float* x     = (const float*)d_in[0];
    const float* cross = (const float*)d_in[1];
    const float* Wq_s = (const float*)d_in[2];  const float* bq_s = (const float*)d_in[3];
    const float* Wk_s = (const float*)d_in[4];  const float* bk_s = (const float*)d_in[5];
    const float* Wv_s = (const float*)d_in[6];  const float* bv_s = (const float*)d_in[7];
    const float* Wo_s = (const float*)d_in[8];  const float* bo_s = (const float*)d_in[9];
    const float* Wq_c = (const float*)d_in[10]; const float* bq_c = (const float*)d_in[11];
    const float* Wk_c = (const float*)d_in[12]; const float* bk_c = (const float*)d_in[13];
    const float* Wv_c = (const float*)d_in[14]; const float* bv_c = (const float*)d_in[15];
    const float* Wo_c = (const float*)d_in[16]; const float* bo_c = (const float*)d_in[17];
    const float* g1 = (const float*)d_in[18]; const float* b1 = (const float*)d_in[19];
    const float* g2 = (const float*)d_in[20]; const float* b2 = (const float*)d_in[21];
    const float* g3 = (const float*)d_in[22]; const float* b3 = (const float*)d_in[23];
    const float* W_ih = (const float*)d_in[24];
    const float* W_hh = (const float*)d_in[25];
    const float* b_ih = (const float*)d_in[26];
    const float* b_hh = (const float*)d_in[27];
    const float* Wc = (const float*)d_in[28]; const float* bc = (const float*)d_in[29];
    float* out = (float*)d_out;

    float *gq, *gk, *gv, *gctx, *gx1, *gx2, *gtmp, *gyt, *gY;
    cudaGetSymbolAddress((void**)&gq,   g_q);
    cudaGetSymbolAddress((void**)&gk,   g_k);
    cudaGetSymbolAddress((void**)&gv,   g_v);
    cudaGetSymbolAddress((void**)&gctx, g_ctx);
    cudaGetSymbolAddress((void**)&gx1,  g_x1);
    cudaGetSymbolAddress((void**)&gx2,  g_x2);
    cudaGetSymbolAddress((void**)&gtmp, g_tmp);
    cudaGetSymbolAddress((void**)&gyt,  g_yt);
    cudaGetSymbolAddress((void**)&gY,   g_Y);

    const int M1 = 3200;    // B*L
    zero_flags_kernel<<<17, 256>>>();

    // ---- self attention ----
    {
        GemmSet s = {{Wq_s, Wk_s, Wv_s}, {bq_s, bk_s, bv_s},
                     {nullptr, nullptr, nullptr}, {gq, gk, gv}};
        gemm_db_kernel<false><<<dim3(25, 8, 3), 256>>>(x, s);
    }
    attn_kernel<<<128 * 8, 128>>>(gq, gk, gv, gctx, 25);
    {
        GemmSet s = {{Wo_s, nullptr, nullptr}, {bo_s, nullptr, nullptr},
                     {x, nullptr, nullptr}, {gtmp, nullptr, nullptr}};
        gemm_db_kernel<false><<<dim3(25, 8, 1), 256>>>(gctx, s);
    }
    ln_kernel<<<M1 / 8, 256>>>(gtmp, g1, b1, gx1, M1);

    // ---- cross attention ----
    {
        GemmSet s = {{Wq_c, nullptr, nullptr}, {bq_c, nullptr, nullptr},
                     {nullptr, nullptr, nullptr}, {gq, nullptr, nullptr}};
        gemm_db_kernel<false><<<dim3(25, 8, 1), 256>>>(gx1, s);
    }
    {
        GemmSet s = {{Wk_c, Wv_c, nullptr}, {bk_c, bv_c, nullptr},
                     {nullptr, nullptr, nullptr}, {gk, gv, nullptr}};
        gemm_db_kernel<false><<<dim3(96, 8, 2), 256>>>(cross, s);
    }
    attn_kernel<<<128 * 8, 128>>>(gq, gk, gv, gctx, 96);
    {
        GemmSet s = {{Wo_c, nullptr, nullptr}, {bo_c, nullptr, nullptr},
                     {gx1, nullptr, nullptr}, {gtmp, nullptr, nullptr}};
        gemm_db_kernel<false><<<dim3(25, 8, 1), 256>>>(gctx, s);
    }
    ln_kernel<<<M1 / 8, 256>>>(gtmp, g2, b2, gx2, M1);

    // ---- LSTM wavefront over feature axis ----
    transpose_in_kernel<<<(128 * 512 * 25 + 255) / 256, 256>>>(gx2, gY);
    lstm_wave_kernel<<<128, 256>>>(W_ih, W_hh, b_ih, b_hh);

    // ---- pointwise conv + residual + final LN ----
    transpose_out_kernel<<<(128 * 25 * 512 + 255) / 256, 256>>>(gY + 32ull * YSTRIDE, gyt);
    {
        GemmSet s = {{Wc, nullptr, nullptr}, {bc, nullptr, nullptr},
                     {gx2, nullptr, nullptr}, {gtmp, nullptr, nullptr}};
        gemm_db_kernel<true><<<dim3(25, 8, 1), 256>>>(gyt, s);
    }
    ln_kernel<<<M1 / 8, 256>>>(gtmp, g3, b3, out, M1);
}